// round 12
// baseline (speedup 1.0000x reference)
#include <cuda_runtime.h>
#include <math.h>

#define EPS 1e-8f
#define B 64
#define N 1024
#define W 128

// Output layout (flattened concat of the 4 outputs)
#define OFF_W    ((size_t)0)
#define OFF_MEM  ((size_t)(B*N))                       // 65536
#define OFF_LINK ((size_t)(B*N) + (size_t)B*N*W)       // 8454144
#define OFF_PREC (OFF_LINK + (size_t)B*N*N)            // 75563008

__device__ __forceinline__ float softplus1(float x) {
    if (x > 20.f) return 1.f + x;
    return 1.f + log1pf(expf(x));
}
__device__ __forceinline__ float sigmoidf_(float x) {
    return 1.f / (1.f + expf(-x));
}
__device__ __forceinline__ float warp_sum(float v) {
    #pragma unroll
    for (int o = 16; o > 0; o >>= 1) v += __shfl_xor_sync(0xFFFFFFFFu, v, o);
    return v;
}
__device__ __forceinline__ float warp_max(float v) {
    #pragma unroll
    for (int o = 16; o > 0; o >>= 1) v = fmaxf(v, __shfl_xor_sync(0xFFFFFFFFu, v, o));
    return v;
}

// ---------------------------------------------------------------------------
// sim_kernel: cosine similarity * beta for all (b,n) rows, fused with the
// memory passthrough. ILP version: all 8 row-loads front-batched into regs
// (MLP=8), passthrough stores issued immediately, then the 16 independent
// shuffle-reduction chains run overlapped.
// Grid: B*16 blocks of 256 threads (8 warps). Each block: 64 rows of one batch.
// ---------------------------------------------------------------------------
#define SIM_BLOCKS_PER_B 16
#define SIM_ROWS_PER_BLOCK (N / SIM_BLOCKS_PER_B)   // 64
#define SIM_ROWS_PER_WARP  (SIM_ROWS_PER_BLOCK / 8) // 8

__global__ __launch_bounds__(256) void sim_kernel(
    const float* __restrict__ w_key,    // (B,W)
    const float* __restrict__ w_beta,   // (B,1)
    const float* __restrict__ memory,   // (B,N,W)
    float* __restrict__ out)            // full out buffer
{
    const int blk = blockIdx.x;
    const int b = blk / SIM_BLOCKS_PER_B;
    const int n0 = (blk % SIM_BLOCKS_PER_B) * SIM_ROWS_PER_BLOCK;
    const int tid = threadIdx.x;
    const int lane = tid & 31;
    const int wid  = tid >> 5;

    __shared__ float sk[W];
    __shared__ float s_scale;   // beta / knorm

    if (tid < W) sk[tid] = w_key[(size_t)b * W + tid];
    __syncthreads();

    if (wid == 0) {
        float s = 0.f;
        #pragma unroll
        for (int c = 0; c < W / 32; c++) {
            float v = sk[lane + 32 * c];
            s += v * v;
        }
        s = warp_sum(s);
        if (lane == 0) {
            float knorm = sqrtf(s) + EPS;
            s_scale = softplus1(w_beta[b]) / knorm;
        }
    }
    __syncthreads();
    const float scale = s_scale;

    const float4 kk = ((const float4*)sk)[lane];
    float* out_mem = out + OFF_MEM;
    float* sim_stash = out + OFF_PREC;   // temporary home for sims

    const int nbase = n0 + wid * SIM_ROWS_PER_WARP;
    const size_t base = ((size_t)b * N + nbase) * W;

    // Phase 1: front-batch all 8 row loads (8 independent LDG.128 in flight)
    float4 v[SIM_ROWS_PER_WARP];
    #pragma unroll
    for (int r = 0; r < SIM_ROWS_PER_WARP; r++)
        v[r] = ((const float4*)(memory + base + (size_t)r * W))[lane];

    // Phase 2: passthrough stores (issue-only, don't block)
    #pragma unroll
    for (int r = 0; r < SIM_ROWS_PER_WARP; r++)
        ((float4*)(out_mem + base + (size_t)r * W))[lane] = v[r];

    // Phase 3: 8x2 independent reduction chains, overlapped
    float dot[SIM_ROWS_PER_WARP], ss[SIM_ROWS_PER_WARP];
    #pragma unroll
    for (int r = 0; r < SIM_ROWS_PER_WARP; r++) {
        dot[r] = v[r].x * kk.x + v[r].y * kk.y + v[r].z * kk.z + v[r].w * kk.w;
        ss[r]  = v[r].x * v[r].x + v[r].y * v[r].y + v[r].z * v[r].z + v[r].w * v[r].w;
    }
    #pragma unroll
    for (int o = 16; o > 0; o >>= 1) {
        #pragma unroll
        for (int r = 0; r < SIM_ROWS_PER_WARP; r++) {
            dot[r] += __shfl_xor_sync(0xFFFFFFFFu, dot[r], o);
            ss[r]  += __shfl_xor_sync(0xFFFFFFFFu, ss[r], o);
        }
    }
    if (lane == 0) {
        #pragma unroll
        for (int r = 0; r < SIM_ROWS_PER_WARP; r++)
            sim_stash[(size_t)b * N + nbase + r] = dot[r] / (sqrtf(ss[r]) + EPS) * scale;
    }
}

// ---------------------------------------------------------------------------
// finish_kernel: softmax over sims, gates, w_weights, precedence_new.
// One block per batch, 1024 threads. Reads sim from out+OFF_PREC, then
// overwrites that same element with precedence_new (read-before-write per
// thread; no cross-thread hazard).
// ---------------------------------------------------------------------------
__global__ __launch_bounds__(1024) void finish_kernel(
    const float* __restrict__ a_gate,   // (B,1)
    const float* __restrict__ w_gate,   // (B,1)
    const float* __restrict__ alloc,    // (B,N)
    const float* __restrict__ prec,     // (B,N)
    float* __restrict__ out)
{
    const int b = blockIdx.x;
    const int tid = threadIdx.x;
    const int lane = tid & 31;
    const int wid  = tid >> 5;

    __shared__ float sred[32];
    __shared__ float sbr;

    float x = out[OFF_PREC + (size_t)b * N + tid];   // stashed sim

    // block max
    float m = warp_max(x);
    if (lane == 0) sred[wid] = m;
    __syncthreads();
    if (wid == 0) {
        float mm = warp_max(sred[lane]);
        if (lane == 0) sbr = mm;
    }
    __syncthreads();
    const float mx = sbr;

    // block sum of exp
    float e = expf(x - mx);
    float s = warp_sum(e);
    if (lane == 0) sred[wid] = s;
    __syncthreads();
    if (wid == 0) {
        float t = warp_sum(sred[lane]);
        if (lane == 0) sbr = t;
    }
    __syncthreads();
    const float c_w = e / sbr;

    const float ag = sigmoidf_(a_gate[b]);
    const float wg = sigmoidf_(w_gate[b]);
    const float w = wg * (ag * alloc[(size_t)b * N + tid] + (1.f - ag) * c_w);

    out[OFF_W + (size_t)b * N + tid] = w;

    // block sum of w for precedence update
    float ws = warp_sum(w);
    if (lane == 0) sred[wid] = ws;
    __syncthreads();
    if (wid == 0) {
        float t = warp_sum(sred[lane]);
        if (lane == 0) sbr = t;
    }
    __syncthreads();
    const float wsum = sbr;
    const float p = prec[(size_t)b * N + tid];
    out[OFF_PREC + (size_t)b * N + tid] = (1.f - wsum) * p + w;
}

// ---------------------------------------------------------------------------
// link_kernel: link[b,i,j] = (1 - w_i - w_j)*L[b,i,j] + w_i*p_j, diag = 0
// One block handles 4 consecutive rows of one batch; loads front-batched
// (MLP_p1 = 4) for latency hiding. 256 threads x float4 covers N = 1024.
// ---------------------------------------------------------------------------
#define ROWS_PER_BLK 4
__global__ __launch_bounds__(256) void link_kernel(
    const float* __restrict__ link_in,   // (B,N,N)
    const float* __restrict__ w,         // w_weights (in out buffer)
    const float* __restrict__ p,         // precedence input
    float* __restrict__ link_out)
{
    const int blk = blockIdx.x;
    const int row0 = blk * ROWS_PER_BLK;         // b*N + i0
    const int b = row0 >> 10;
    const int i0 = row0 & (N - 1);
    const int tid = threadIdx.x;

    const float4 wj = ((const float4*)(w + (size_t)b * N))[tid];
    const float4 pj = ((const float4*)(p + (size_t)b * N))[tid];
    const int j0 = tid << 2;

    // front-batched loads: 4 independent LDG.128 in flight
    float4 L[ROWS_PER_BLK];
    float wi[ROWS_PER_BLK];
    #pragma unroll
    for (int r = 0; r < ROWS_PER_BLK; r++) {
        const size_t rowoff = ((size_t)row0 + r) * N;
        L[r] = ((const float4*)(link_in + rowoff))[tid];
        wi[r] = __ldg(&w[(size_t)b * N + i0 + r]);
    }

    #pragma unroll
    for (int r = 0; r < ROWS_PER_BLK; r++) {
        const int i = i0 + r;
        const float omwi = 1.f - wi[r];
        float4 o;
        o.x = (omwi - wj.x) * L[r].x + wi[r] * pj.x;
        o.y = (omwi - wj.y) * L[r].y + wi[r] * pj.y;
        o.z = (omwi - wj.z) * L[r].z + wi[r] * pj.z;
        o.w = (omwi - wj.w) * L[r].w + wi[r] * pj.w;
        if (i >= j0 && i < j0 + 4) ((float*)&o)[i - j0] = 0.f;
        ((float4*)(link_out + ((size_t)row0 + r) * N))[tid] = o;
    }
}

extern "C" void kernel_launch(void* const* d_in, const int* in_sizes, int n_in,
                              void* d_out, int out_size) {
    const float* w_key    = (const float*)d_in[0];
    const float* w_beta   = (const float*)d_in[1];
    // d_in[2] = e_vector (unused), d_in[3] = w_vector (unused)
    const float* a_gate   = (const float*)d_in[4];
    const float* w_gate   = (const float*)d_in[5];
    const float* alloc    = (const float*)d_in[6];
    const float* memory   = (const float*)d_in[7];
    const float* link_in  = (const float*)d_in[8];
    const float* prec     = (const float*)d_in[9];
    float* out = (float*)d_out;

    // 1) similarities (stashed in out+OFF_PREC) + fused memory passthrough
    sim_kernel<<<B * SIM_BLOCKS_PER_B, 256>>>(w_key, w_beta, memory, out);

    // 2) softmax + gates + w_weights + precedence_new (overwrites stash)
    finish_kernel<<<B, 1024>>>(a_gate, w_gate, alloc, prec, out);

    // 3) link update (reads w_weights written by finish_kernel; same stream)
    link_kernel<<<(B * N) / ROWS_PER_BLK, 256>>>(link_in, out + OFF_W, prec, out + OFF_LINK);
}

// round 13
// speedup vs baseline: 1.0309x; 1.0309x over previous
#include <cuda_runtime.h>
#include <math.h>

#define EPS 1e-8f
#define B 64
#define N 1024
#define W 128

// Output layout (flattened concat of the 4 outputs)
#define OFF_W    ((size_t)0)
#define OFF_MEM  ((size_t)(B*N))                       // 65536
#define OFF_LINK ((size_t)(B*N) + (size_t)B*N*W)       // 8454144
#define OFF_PREC (OFF_LINK + (size_t)B*N*N)            // 75563008

__device__ __forceinline__ float softplus1(float x) {
    if (x > 20.f) return 1.f + x;
    return 1.f + log1pf(expf(x));
}
__device__ __forceinline__ float sigmoidf_(float x) {
    return 1.f / (1.f + expf(-x));
}
__device__ __forceinline__ float warp_sum(float v) {
    #pragma unroll
    for (int o = 16; o > 0; o >>= 1) v += __shfl_xor_sync(0xFFFFFFFFu, v, o);
    return v;
}
__device__ __forceinline__ float warp_max(float v) {
    #pragma unroll
    for (int o = 16; o > 0; o >>= 1) v = fmaxf(v, __shfl_xor_sync(0xFFFFFFFFu, v, o));
    return v;
}

// ---------------------------------------------------------------------------
// sim_kernel v3: 8-lanes-per-row layout to minimize SHFL count.
// Each warp iteration covers 4 rows (lane>>3 = local row, lane&7 = slice);
// each thread loads 4 float4 chunks of its row (MLP=4), fused passthrough
// store, accumulates dot/ss in registers, then a 3-step 8-lane shuffle
// reduction. Per 8 rows: 12 SHFLs (vs 80 in the warp-per-row layout).
// Grid: B*16 blocks of 256 threads (8 warps); block covers 64 rows.
// ---------------------------------------------------------------------------
#define SIM_BLOCKS_PER_B 16
#define SIM_ROWS_PER_BLOCK (N / SIM_BLOCKS_PER_B)   // 64
#define SIM_ROWS_PER_WARP  (SIM_ROWS_PER_BLOCK / 8) // 8
#define SIM_ITERS          (SIM_ROWS_PER_WARP / 4)  // 2

__global__ __launch_bounds__(256) void sim_kernel(
    const float* __restrict__ w_key,    // (B,W)
    const float* __restrict__ w_beta,   // (B,1)
    const float* __restrict__ memory,   // (B,N,W)
    float* __restrict__ out)            // full out buffer
{
    const int blk = blockIdx.x;
    const int b = blk / SIM_BLOCKS_PER_B;
    const int n0 = (blk % SIM_BLOCKS_PER_B) * SIM_ROWS_PER_BLOCK;
    const int tid = threadIdx.x;
    const int lane = tid & 31;
    const int wid  = tid >> 5;
    const int rloc = lane >> 3;     // 0..3: local row within 4-row group
    const int slice = lane & 7;     // 0..7: which 16-float slice of the row

    __shared__ float sk[W];
    __shared__ float s_scale;   // beta / knorm

    if (tid < W) sk[tid] = w_key[(size_t)b * W + tid];
    __syncthreads();

    if (wid == 0) {
        float s = 0.f;
        #pragma unroll
        for (int c = 0; c < W / 32; c++) {
            float v = sk[lane + 32 * c];
            s += v * v;
        }
        s = warp_sum(s);
        if (lane == 0) {
            float knorm = sqrtf(s) + EPS;
            s_scale = softplus1(w_beta[b]) / knorm;
        }
    }
    __syncthreads();
    const float scale = s_scale;

    // this thread's 4 key chunks (float4 index = slice + c*8)
    const float4* k4 = (const float4*)sk;
    float4 kc[4];
    #pragma unroll
    for (int c = 0; c < 4; c++) kc[c] = k4[slice + c * 8];

    float* out_mem = out + OFF_MEM;
    float* sim_stash = out + OFF_PREC;   // temporary home for sims

    #pragma unroll
    for (int it = 0; it < SIM_ITERS; it++) {
        const int n = n0 + wid * SIM_ROWS_PER_WARP + it * 4 + rloc;
        const size_t roff = ((size_t)b * N + n) * W;
        const float4* row4 = (const float4*)(memory + roff);
        float4* orow4 = (float4*)(out_mem + roff);

        // 4 independent LDG.128 in flight
        float4 v[4];
        #pragma unroll
        for (int c = 0; c < 4; c++) v[c] = row4[slice + c * 8];

        // fused passthrough stores
        #pragma unroll
        for (int c = 0; c < 4; c++) orow4[slice + c * 8] = v[c];

        float dot = 0.f, ss = 0.f;
        #pragma unroll
        for (int c = 0; c < 4; c++) {
            dot += v[c].x * kc[c].x + v[c].y * kc[c].y + v[c].z * kc[c].z + v[c].w * kc[c].w;
            ss  += v[c].x * v[c].x + v[c].y * v[c].y + v[c].z * v[c].z + v[c].w * v[c].w;
        }

        // 3-step reduction within the 8-lane group
        #pragma unroll
        for (int o = 4; o > 0; o >>= 1) {
            dot += __shfl_xor_sync(0xFFFFFFFFu, dot, o);
            ss  += __shfl_xor_sync(0xFFFFFFFFu, ss, o);
        }
        if (slice == 0)
            sim_stash[(size_t)b * N + n] = dot / (sqrtf(ss) + EPS) * scale;
    }
}

// ---------------------------------------------------------------------------
// finish_kernel: softmax over sims, gates, w_weights, precedence_new.
// One block per batch, 1024 threads. Reads sim from out+OFF_PREC, then
// overwrites that same element with precedence_new (read-before-write per
// thread; no cross-thread hazard).
// ---------------------------------------------------------------------------
__global__ __launch_bounds__(1024) void finish_kernel(
    const float* __restrict__ a_gate,   // (B,1)
    const float* __restrict__ w_gate,   // (B,1)
    const float* __restrict__ alloc,    // (B,N)
    const float* __restrict__ prec,     // (B,N)
    float* __restrict__ out)
{
    const int b = blockIdx.x;
    const int tid = threadIdx.x;
    const int lane = tid & 31;
    const int wid  = tid >> 5;

    __shared__ float sred[32];
    __shared__ float sbr;

    float x = out[OFF_PREC + (size_t)b * N + tid];   // stashed sim

    // block max
    float m = warp_max(x);
    if (lane == 0) sred[wid] = m;
    __syncthreads();
    if (wid == 0) {
        float mm = warp_max(sred[lane]);
        if (lane == 0) sbr = mm;
    }
    __syncthreads();
    const float mx = sbr;

    // block sum of exp
    float e = expf(x - mx);
    float s = warp_sum(e);
    if (lane == 0) sred[wid] = s;
    __syncthreads();
    if (wid == 0) {
        float t = warp_sum(sred[lane]);
        if (lane == 0) sbr = t;
    }
    __syncthreads();
    const float c_w = e / sbr;

    const float ag = sigmoidf_(a_gate[b]);
    const float wg = sigmoidf_(w_gate[b]);
    const float w = wg * (ag * alloc[(size_t)b * N + tid] + (1.f - ag) * c_w);

    out[OFF_W + (size_t)b * N + tid] = w;

    // block sum of w for precedence update
    float ws = warp_sum(w);
    if (lane == 0) sred[wid] = ws;
    __syncthreads();
    if (wid == 0) {
        float t = warp_sum(sred[lane]);
        if (lane == 0) sbr = t;
    }
    __syncthreads();
    const float wsum = sbr;
    const float p = prec[(size_t)b * N + tid];
    out[OFF_PREC + (size_t)b * N + tid] = (1.f - wsum) * p + w;
}

// ---------------------------------------------------------------------------
// link_kernel: link[b,i,j] = (1 - w_i - w_j)*L[b,i,j] + w_i*p_j, diag = 0
// One block handles 4 consecutive rows of one batch; loads front-batched
// (MLP_p1 = 4) for latency hiding. 256 threads x float4 covers N = 1024.
// ---------------------------------------------------------------------------
#define ROWS_PER_BLK 4
__global__ __launch_bounds__(256) void link_kernel(
    const float* __restrict__ link_in,   // (B,N,N)
    const float* __restrict__ w,         // w_weights (in out buffer)
    const float* __restrict__ p,         // precedence input
    float* __restrict__ link_out)
{
    const int blk = blockIdx.x;
    const int row0 = blk * ROWS_PER_BLK;         // b*N + i0
    const int b = row0 >> 10;
    const int i0 = row0 & (N - 1);
    const int tid = threadIdx.x;

    const float4 wj = ((const float4*)(w + (size_t)b * N))[tid];
    const float4 pj = ((const float4*)(p + (size_t)b * N))[tid];
    const int j0 = tid << 2;

    // front-batched loads: 4 independent LDG.128 in flight
    float4 L[ROWS_PER_BLK];
    float wi[ROWS_PER_BLK];
    #pragma unroll
    for (int r = 0; r < ROWS_PER_BLK; r++) {
        const size_t rowoff = ((size_t)row0 + r) * N;
        L[r] = ((const float4*)(link_in + rowoff))[tid];
        wi[r] = __ldg(&w[(size_t)b * N + i0 + r]);
    }

    #pragma unroll
    for (int r = 0; r < ROWS_PER_BLK; r++) {
        const int i = i0 + r;
        const float omwi = 1.f - wi[r];
        float4 o;
        o.x = (omwi - wj.x) * L[r].x + wi[r] * pj.x;
        o.y = (omwi - wj.y) * L[r].y + wi[r] * pj.y;
        o.z = (omwi - wj.z) * L[r].z + wi[r] * pj.z;
        o.w = (omwi - wj.w) * L[r].w + wi[r] * pj.w;
        if (i >= j0 && i < j0 + 4) ((float*)&o)[i - j0] = 0.f;
        ((float4*)(link_out + ((size_t)row0 + r) * N))[tid] = o;
    }
}

extern "C" void kernel_launch(void* const* d_in, const int* in_sizes, int n_in,
                              void* d_out, int out_size) {
    const float* w_key    = (const float*)d_in[0];
    const float* w_beta   = (const float*)d_in[1];
    // d_in[2] = e_vector (unused), d_in[3] = w_vector (unused)
    const float* a_gate   = (const float*)d_in[4];
    const float* w_gate   = (const float*)d_in[5];
    const float* alloc    = (const float*)d_in[6];
    const float* memory   = (const float*)d_in[7];
    const float* link_in  = (const float*)d_in[8];
    const float* prec     = (const float*)d_in[9];
    float* out = (float*)d_out;

    // 1) similarities (stashed in out+OFF_PREC) + fused memory passthrough
    sim_kernel<<<B * SIM_BLOCKS_PER_B, 256>>>(w_key, w_beta, memory, out);

    // 2) softmax + gates + w_weights + precedence_new (overwrites stash)
    finish_kernel<<<B, 1024>>>(a_gate, w_gate, alloc, prec, out);

    // 3) link update (reads w_weights written by finish_kernel; same stream)
    link_kernel<<<(B * N) / ROWS_PER_BLK, 256>>>(link_in, out + OFF_W, prec, out + OFF_LINK);
}